// round 6
// baseline (speedup 1.0000x reference)
#include <cuda_runtime.h>
#include <cstdint>
#include <cfloat>

#define EPS 1e-5f

// B=4, C=64, N=4096, OUT=128, K=20, DIL=2

// ---------------- scratch (device globals; no allocation allowed) ----------------
__device__ __align__(16) float g_rt[4 * 4096 * 128];   // residual, transposed [b][n][o]
__device__ __align__(16) float g_hb[4 * 4096 * 16];    // bottleneck features [b][n][ch]
__device__ __align__(16) float g_sq[4 * 4096];         // squared norms
__device__ int   g_idx[4 * 4096 * 20];                 // knn indices
__device__ __align__(16) float g_wdt[96 * 128];        // folded + transposed W_dec [j][o]

// ---------------- f32x2 helpers (Blackwell packed fp32) ----------------
__device__ __forceinline__ unsigned long long fma2(unsigned long long a,
                                                   unsigned long long b,
                                                   unsigned long long c) {
    unsigned long long d;
    asm("fma.rn.f32x2 %0, %1, %2, %3;" : "=l"(d) : "l"(a), "l"(b), "l"(c));
    return d;
}
__device__ __forceinline__ unsigned long long pack2(float f) {
    unsigned long long d;
    unsigned u = __float_as_uint(f);
    asm("mov.b64 %0, {%1, %2};" : "=l"(d) : "r"(u), "r"(u));
    return d;
}
__device__ __forceinline__ void unpack2(unsigned long long a, float& lo, float& hi) {
    unsigned ulo, uhi;
    asm("mov.b64 {%0, %1}, %2;" : "=r"(ulo), "=r"(uhi) : "l"(a));
    lo = __uint_as_float(ulo); hi = __uint_as_float(uhi);
}

// =====================================================================
// Kernel 1: prologue — residual conv (BN+ReLU folded), bottleneck conv,
//           squared norms.  128 threads = 128 points, grid (32, B).
// =====================================================================
__global__ void __launch_bounds__(128) k_prologue(
    const float* __restrict__ x,
    const float* __restrict__ Wr, const float* __restrict__ gr, const float* __restrict__ br,
    const float* __restrict__ mr, const float* __restrict__ vr,
    const float* __restrict__ Wb, const float* __restrict__ gb, const float* __restrict__ bbi,
    const float* __restrict__ mb, const float* __restrict__ vb)
{
    __shared__ __align__(16) float Wrs[128 * 64];
    __shared__ __align__(16) float Wbs[16 * 64];
    __shared__ float srs[128], trs[128], sbs[16], tbs[16];

    int t = threadIdx.x;
    int b = blockIdx.y;
    int n = blockIdx.x * 128 + t;

    { float s = gr[t] * rsqrtf(vr[t] + EPS); srs[t] = s; trs[t] = br[t] - mr[t] * s; }
    if (t < 16) { float s = gb[t] * rsqrtf(vb[t] + EPS); sbs[t] = s; tbs[t] = bbi[t] - mb[t] * s; }
    __syncthreads();
    for (int li = t; li < 128 * 64; li += 128) Wrs[li] = Wr[li] * srs[li >> 6];
    for (int li = t; li < 16 * 64; li += 128)  Wbs[li] = Wb[li] * sbs[li >> 6];
    __syncthreads();

    float xq[64];
    const float* xp = x + (size_t)b * 64 * 4096 + n;
#pragma unroll
    for (int c = 0; c < 64; ++c) xq[c] = xp[c * 4096];

    float sq = 0.f;
#pragma unroll
    for (int c = 0; c < 64; ++c) sq = fmaf(xq[c], xq[c], sq);
    g_sq[b * 4096 + n] = sq;

    float* rout = g_rt + (size_t)(b * 4096 + n) * 128;
#pragma unroll 1
    for (int o0 = 0; o0 < 128; o0 += 4) {
        float acc[4];
#pragma unroll
        for (int r = 0; r < 4; ++r) acc[r] = trs[o0 + r];
#pragma unroll
        for (int c4 = 0; c4 < 16; ++c4) {
#pragma unroll
            for (int r = 0; r < 4; ++r) {
                float4 w = *(const float4*)&Wrs[(o0 + r) * 64 + c4 * 4];
                acc[r] = fmaf(w.x, xq[c4 * 4 + 0], acc[r]);
                acc[r] = fmaf(w.y, xq[c4 * 4 + 1], acc[r]);
                acc[r] = fmaf(w.z, xq[c4 * 4 + 2], acc[r]);
                acc[r] = fmaf(w.w, xq[c4 * 4 + 3], acc[r]);
            }
        }
        float4 o;
        o.x = fmaxf(acc[0], 0.f); o.y = fmaxf(acc[1], 0.f);
        o.z = fmaxf(acc[2], 0.f); o.w = fmaxf(acc[3], 0.f);
        *(float4*)&rout[o0] = o;
    }

    float* hout = g_hb + (size_t)(b * 4096 + n) * 16;
#pragma unroll 1
    for (int o0 = 0; o0 < 16; o0 += 4) {
        float acc[4];
#pragma unroll
        for (int r = 0; r < 4; ++r) acc[r] = tbs[o0 + r];
#pragma unroll
        for (int c4 = 0; c4 < 16; ++c4) {
#pragma unroll
            for (int r = 0; r < 4; ++r) {
                float4 w = *(const float4*)&Wbs[(o0 + r) * 64 + c4 * 4];
                acc[r] = fmaf(w.x, xq[c4 * 4 + 0], acc[r]);
                acc[r] = fmaf(w.y, xq[c4 * 4 + 1], acc[r]);
                acc[r] = fmaf(w.z, xq[c4 * 4 + 2], acc[r]);
                acc[r] = fmaf(w.w, xq[c4 * 4 + 3], acc[r]);
            }
        }
        float4 o;
        o.x = fmaxf(acc[0], 0.f); o.y = fmaxf(acc[1], 0.f);
        o.z = fmaxf(acc[2], 0.f); o.w = fmaxf(acc[3], 0.f);
        *(float4*)&hout[o0] = o;
    }
}

// =====================================================================
// Kernel 2: fold W_dec with BN scale and transpose to [j][o]
// =====================================================================
__global__ void k_foldw(const float* __restrict__ Wd, const float* __restrict__ gd,
                        const float* __restrict__ vd)
{
    int li = blockIdx.x * blockDim.x + threadIdx.x;
    if (li < 96 * 128) {
        int j = li >> 7, o = li & 127;
        float s = gd[o] * rsqrtf(vd[o] + EPS);
        g_wdt[li] = Wd[o * 96 + j] * s;
    }
}

// =====================================================================
// Kernel 3: KNN.  256 threads = 64 queries x 4 candidate-splits,
// grid (64, B).  f32x2 packed dot products; register top-20 with stable
// (d, idx) ordering; 4-way stable merge by split 0.
// =====================================================================
struct KP1 { float xm[64][128]; float sqm[128]; };
struct KP2 { float d[64][4][20]; int id[64][4][20]; };
union __align__(16) KSm { KP1 p1; KP2 p2; };

__global__ void __launch_bounds__(256) k_knn(const float* __restrict__ x)
{
    __shared__ KSm sm;
    int t = threadIdx.x;
    int s = t >> 6, q = t & 63;
    int b = blockIdx.y;
    int qg = blockIdx.x * 64 + q;

    float qc[64];
    const float* xp = x + (size_t)b * 64 * 4096 + qg;
#pragma unroll
    for (int c = 0; c < 64; ++c) qc[c] = xp[c * 4096];

    float topd[20]; int topi[20];
#pragma unroll
    for (int j = 0; j < 20; ++j) { topd[j] = FLT_MAX; topi[j] = 0x7fffffff; }

    const float* xb = x + (size_t)b * 64 * 4096;
#pragma unroll 1
    for (int tile = 0; tile < 32; ++tile) {
        int m0 = tile * 128;
        for (int li = t * 4; li < 64 * 128; li += 1024) {
            int c = li >> 7, m = li & 127;
            *(float4*)&sm.p1.xm[c][m] = *(const float4*)&xb[c * 4096 + m0 + m];
        }
        if (t < 32)
            *(float4*)&sm.p1.sqm[t * 4] = *(const float4*)&g_sq[b * 4096 + m0 + t * 4];
        __syncthreads();

#pragma unroll 1
        for (int oi = 0; oi < 4; ++oi) {
            int oct = s + oi * 4;   // this split handles candidates m0 + oct*8 .. +7
            unsigned long long a0 = 0, a1 = 0, a2 = 0, a3 = 0;
#pragma unroll
            for (int c = 0; c < 64; ++c) {
                unsigned long long qq = pack2(qc[c]);
                const ulonglong2* row = (const ulonglong2*)&sm.p1.xm[c][oct * 8];
                ulonglong2 v0 = row[0];
                ulonglong2 v1 = row[1];
                a0 = fma2(qq, v0.x, a0);
                a1 = fma2(qq, v0.y, a1);
                a2 = fma2(qq, v1.x, a2);
                a3 = fma2(qq, v1.y, a3);
            }
            float dd[8];
            unpack2(a0, dd[0], dd[1]); unpack2(a1, dd[2], dd[3]);
            unpack2(a2, dd[4], dd[5]); unpack2(a3, dd[6], dd[7]);
#pragma unroll
            for (int j = 0; j < 8; ++j) {
                int mm = oct * 8 + j;
                float v = fmaf(-2.f, dd[j], sm.p1.sqm[mm]);   // rank key; sq[query] dropped
                if (v < topd[19]) {
                    float dv = v; int mi = m0 + mm;
#pragma unroll
                    for (int jj = 0; jj < 20; ++jj) {
                        if (dv < topd[jj]) {
                            float td = topd[jj]; topd[jj] = dv; dv = td;
                            int ti = topi[jj]; topi[jj] = mi; mi = ti;
                        }
                    }
                }
            }
        }
        __syncthreads();
    }

#pragma unroll
    for (int j = 0; j < 20; ++j) { sm.p2.d[q][s][j] = topd[j]; sm.p2.id[q][s][j] = topi[j]; }
    __syncthreads();

    if (s == 0) {
        int p0 = 0, p1 = 0, p2 = 0, p3 = 0;
        int* op = g_idx + (size_t)(b * 4096 + qg) * 20;
        for (int k = 0; k < 20; ++k) {
            float bd = sm.p2.d[q][0][p0]; int bi = sm.p2.id[q][0][p0]; int bl = 0;
            float d1 = sm.p2.d[q][1][p1]; int i1 = sm.p2.id[q][1][p1];
            if (d1 < bd || (d1 == bd && i1 < bi)) { bd = d1; bi = i1; bl = 1; }
            float d2 = sm.p2.d[q][2][p2]; int i2 = sm.p2.id[q][2][p2];
            if (d2 < bd || (d2 == bd && i2 < bi)) { bd = d2; bi = i2; bl = 2; }
            float d3 = sm.p2.d[q][3][p3]; int i3 = sm.p2.id[q][3][p3];
            if (d3 < bd || (d3 == bd && i3 < bi)) { bd = d3; bi = i3; bl = 3; }
            op[k] = bi;
            if (bl == 0) p0++; else if (bl == 1) p1++; else if (bl == 2) p2++; else p3++;
        }
    }
}

// =====================================================================
// Kernel 4: epilogue.  one warp per point (8 points / 256-thr block).
// gather -> gcn1 (K=20) + gcn2 (even k) + global max -> decoder + residual.
// =====================================================================
__global__ void __launch_bounds__(256) k_epilogue(
    const float* __restrict__ Wg1, const float* __restrict__ g1g, const float* __restrict__ g1b,
    const float* __restrict__ g1m, const float* __restrict__ g1v,
    const float* __restrict__ Wg2, const float* __restrict__ g2g, const float* __restrict__ g2b,
    const float* __restrict__ g2m, const float* __restrict__ g2v,
    const float* __restrict__ gdg, const float* __restrict__ gdb,
    const float* __restrict__ gdm, const float* __restrict__ gdv,
    float* __restrict__ out)
{
    __shared__ __align__(16) float W1s[32 * 32];   // [in][out], BN-folded
    __shared__ __align__(16) float W2s[32 * 32];
    __shared__ float t1s[32], t2s[32], s1s[32], s2s[32];
    __shared__ __align__(16) float tds[128];
    __shared__ __align__(16) float fns[8][20][16];
    __shared__ __align__(16) float ctrs[8][16];
    __shared__ float afs[8][96];

    int t = threadIdx.x;
    if (t < 32)      { float s = g1g[t] * rsqrtf(g1v[t] + EPS); s1s[t] = s; t1s[t] = g1b[t] - g1m[t] * s; }
    else if (t < 64) { int i = t - 32; float s = g2g[i] * rsqrtf(g2v[i] + EPS); s2s[i] = s; t2s[i] = g2b[i] - g2m[i] * s; }
    if (t < 128)     { float s = gdg[t] * rsqrtf(gdv[t] + EPS); tds[t] = gdb[t] - gdm[t] * s; }
    __syncthreads();
    for (int li = t; li < 1024; li += 256) {
        int i = li >> 5, o = li & 31;
        W1s[li] = Wg1[o * 32 + i] * s1s[o];
        W2s[li] = Wg2[o * 32 + i] * s2s[o];
    }
    __syncthreads();

    int wid = t >> 5, lane = t & 31;
    int g = blockIdx.x * 8 + wid;
    int b = g >> 12, n = g & 4095;

    float* fw = &fns[wid][0][0];
    float* cw = &ctrs[wid][0];
    float* aw = &afs[wid][0];

    if (lane < 20) {
        int nid = g_idx[(size_t)g * 20 + lane];
        const float4* src = (const float4*)(g_hb + (size_t)(b * 4096 + nid) * 16);
        float4* dst = (float4*)(fw + lane * 16);
        dst[0] = src[0]; dst[1] = src[1]; dst[2] = src[2]; dst[3] = src[3];
    } else if (lane < 24) {
        int j = lane - 20;
        ((float4*)cw)[j] = ((const float4*)(g_hb + (size_t)g * 16))[j];
    }
    __syncwarp();

    float w1[32], w2[32];
#pragma unroll
    for (int i = 0; i < 32; ++i) { w1[i] = W1s[i * 32 + lane]; w2[i] = W2s[i * 32 + lane]; }

    // center contribution (channels 16..31 of the graph feature) hoisted
    float base1 = t1s[lane], base2 = t2s[lane];
#pragma unroll
    for (int j = 0; j < 16; ++j) {
        float cv = cw[j];
        base1 = fmaf(w1[16 + j], cv, base1);
        base2 = fmaf(w2[16 + j], cv, base2);
    }

    float o1 = -FLT_MAX, o2v = -FLT_MAX;
#pragma unroll
    for (int k = 0; k < 20; ++k) {
        const float4* fr = (const float4*)(fw + k * 16);
        float fv[16];
#pragma unroll
        for (int j4 = 0; j4 < 4; ++j4) {
            float4 fq = fr[j4];
            fv[j4 * 4 + 0] = fq.x; fv[j4 * 4 + 1] = fq.y;
            fv[j4 * 4 + 2] = fq.z; fv[j4 * 4 + 3] = fq.w;
        }
        float a = base1;
#pragma unroll
        for (int j = 0; j < 16; ++j) a = fmaf(w1[j], fv[j], a);
        a = a > 0.f ? a : 0.2f * a;        // leaky relu
        o1 = fmaxf(o1, a);
        if ((k & 1) == 0) {                // dilated branch: k = 0,2,...,18
            float a2 = base2;
#pragma unroll
            for (int j = 0; j < 16; ++j) a2 = fmaf(w2[j], fv[j], a2);
            a2 = a2 > 0.f ? a2 : 0.2f * a2;
            o2v = fmaxf(o2v, a2);
        }
    }

    // global max over f1: ch 0..15 = max over neighbors, ch 16..31 = center
    float gm;
    if (lane < 16) {
        gm = fw[lane];
#pragma unroll
        for (int k = 1; k < 20; ++k) gm = fmaxf(gm, fw[k * 16 + lane]);
    } else {
        gm = cw[lane - 16];
    }
    aw[lane] = o1; aw[32 + lane] = o2v; aw[64 + lane] = gm;
    __syncwarp();

    // decoder: lane handles outputs o = 4*lane .. 4*lane+3
    float4 acc = *(const float4*)&tds[lane * 4];
#pragma unroll 4
    for (int j = 0; j < 96; ++j) {
        float a = aw[j];
        float4 w = __ldg((const float4*)&g_wdt[j * 128 + lane * 4]);
        acc.x = fmaf(w.x, a, acc.x); acc.y = fmaf(w.y, a, acc.y);
        acc.z = fmaf(w.z, a, acc.z); acc.w = fmaf(w.w, a, acc.w);
    }
    const float4 rv = *(const float4*)(g_rt + (size_t)g * 128 + lane * 4);
    float r0 = fmaxf(acc.x, 0.f) + rv.x;
    float r1 = fmaxf(acc.y, 0.f) + rv.y;
    float r2 = fmaxf(acc.z, 0.f) + rv.z;
    float r3 = fmaxf(acc.w, 0.f) + rv.w;

    size_t ob = ((size_t)b * 128 + lane * 4) * 4096 + n;   // out[b][o][n][0]
    out[ob]            = r0;
    out[ob + 4096]     = r1;
    out[ob + 2 * 4096] = r2;
    out[ob + 3 * 4096] = r3;
}

// =====================================================================
extern "C" void kernel_launch(void* const* d_in, const int* in_sizes, int n_in,
                              void* d_out, int out_size)
{
    (void)in_sizes; (void)n_in; (void)out_size;
    const float* x    = (const float*)d_in[0];
    const float* Wr   = (const float*)d_in[1];
    const float* gr   = (const float*)d_in[2];
    const float* br   = (const float*)d_in[3];
    const float* mr   = (const float*)d_in[4];
    const float* vr   = (const float*)d_in[5];
    const float* Wb   = (const float*)d_in[6];
    const float* gb   = (const float*)d_in[7];
    const float* bbi  = (const float*)d_in[8];
    const float* mb   = (const float*)d_in[9];
    const float* vb   = (const float*)d_in[10];
    const float* Wg1  = (const float*)d_in[11];
    const float* g1g  = (const float*)d_in[12];
    const float* g1b  = (const float*)d_in[13];
    const float* g1m  = (const float*)d_in[14];
    const float* g1v  = (const float*)d_in[15];
    const float* Wg2  = (const float*)d_in[16];
    const float* g2g  = (const float*)d_in[17];
    const float* g2b  = (const float*)d_in[18];
    const float* g2m  = (const float*)d_in[19];
    const float* g2v  = (const float*)d_in[20];
    const float* Wd   = (const float*)d_in[21];
    const float* gdg  = (const float*)d_in[22];
    const float* gdb  = (const float*)d_in[23];
    const float* gdm  = (const float*)d_in[24];
    const float* gdv  = (const float*)d_in[25];
    float* out = (float*)d_out;

    k_prologue<<<dim3(32, 4), 128>>>(x, Wr, gr, br, mr, vr, Wb, gb, bbi, mb, vb);
    k_foldw<<<48, 256>>>(Wd, gdg, gdv);
    k_knn<<<dim3(64, 4), 256>>>(x);
    k_epilogue<<<2048, 256>>>(Wg1, g1g, g1b, g1m, g1v,
                              Wg2, g2g, g2b, g2m, g2v,
                              gdg, gdb, gdm, gdv, out);
}

// round 8
// speedup vs baseline: 1.0873x; 1.0873x over previous
#include <cuda_runtime.h>
#include <cstdint>
#include <cfloat>

#define EPS 1e-5f

// B=4, C=64, N=4096, OUT=128, K=20, DIL=2

// ---------------- scratch (device globals; no allocation allowed) ----------------
__device__ __align__(16) float g_rt[4 * 4096 * 128];   // residual, transposed [b][n][o]
__device__ __align__(16) float g_hb[4 * 4096 * 16];    // bottleneck features [b][n][ch]
__device__ __align__(16) float g_sq[4 * 4096];         // squared norms
__device__ int   g_idx[4 * 4096 * 20];                 // final knn indices
__device__ __align__(16) float g_wdt[96 * 128];        // folded + transposed W_dec [j][o]
__device__ __align__(16) float g_kd[4 * 8 * 4096 * 20]; // partial top-20 dists [b][list][n][20]
__device__ int   g_ki[4 * 8 * 4096 * 20];               // partial top-20 idx

// ---------------- f32x2 helpers (Blackwell packed fp32) ----------------
__device__ __forceinline__ unsigned long long fma2(unsigned long long a,
                                                   unsigned long long b,
                                                   unsigned long long c) {
    unsigned long long d;
    asm("fma.rn.f32x2 %0, %1, %2, %3;" : "=l"(d) : "l"(a), "l"(b), "l"(c));
    return d;
}
__device__ __forceinline__ unsigned long long pack2(float f) {
    unsigned long long d;
    unsigned u = __float_as_uint(f);
    asm("mov.b64 %0, {%1, %2};" : "=l"(d) : "r"(u), "r"(u));
    return d;
}
__device__ __forceinline__ void unpack2(unsigned long long a, float& lo, float& hi) {
    unsigned ulo, uhi;
    asm("mov.b64 {%0, %1}, %2;" : "=r"(ulo), "=r"(uhi) : "l"(a));
    lo = __uint_as_float(ulo); hi = __uint_as_float(uhi);
}

// =====================================================================
// Kernel 1: prologue — residual conv (BN+ReLU folded), bottleneck conv,
//           squared norms.  128 threads = 128 points, grid (32, B).
// =====================================================================
__global__ void __launch_bounds__(128) k_prologue(
    const float* __restrict__ x,
    const float* __restrict__ Wr, const float* __restrict__ gr, const float* __restrict__ br,
    const float* __restrict__ mr, const float* __restrict__ vr,
    const float* __restrict__ Wb, const float* __restrict__ gb, const float* __restrict__ bbi,
    const float* __restrict__ mb, const float* __restrict__ vb)
{
    __shared__ __align__(16) float Wrs[128 * 64];
    __shared__ __align__(16) float Wbs[16 * 64];
    __shared__ float srs[128], trs[128], sbs[16], tbs[16];

    int t = threadIdx.x;
    int b = blockIdx.y;
    int n = blockIdx.x * 128 + t;

    { float s = gr[t] * rsqrtf(vr[t] + EPS); srs[t] = s; trs[t] = br[t] - mr[t] * s; }
    if (t < 16) { float s = gb[t] * rsqrtf(vb[t] + EPS); sbs[t] = s; tbs[t] = bbi[t] - mb[t] * s; }
    __syncthreads();
    for (int li = t; li < 128 * 64; li += 128) Wrs[li] = Wr[li] * srs[li >> 6];
    for (int li = t; li < 16 * 64; li += 128)  Wbs[li] = Wb[li] * sbs[li >> 6];
    __syncthreads();

    float xq[64];
    const float* xp = x + (size_t)b * 64 * 4096 + n;
#pragma unroll
    for (int c = 0; c < 64; ++c) xq[c] = xp[c * 4096];

    float sq = 0.f;
#pragma unroll
    for (int c = 0; c < 64; ++c) sq = fmaf(xq[c], xq[c], sq);
    g_sq[b * 4096 + n] = sq;

    float* rout = g_rt + (size_t)(b * 4096 + n) * 128;
#pragma unroll 1
    for (int o0 = 0; o0 < 128; o0 += 4) {
        float acc[4];
#pragma unroll
        for (int r = 0; r < 4; ++r) acc[r] = trs[o0 + r];
#pragma unroll
        for (int c4 = 0; c4 < 16; ++c4) {
#pragma unroll
            for (int r = 0; r < 4; ++r) {
                float4 w = *(const float4*)&Wrs[(o0 + r) * 64 + c4 * 4];
                acc[r] = fmaf(w.x, xq[c4 * 4 + 0], acc[r]);
                acc[r] = fmaf(w.y, xq[c4 * 4 + 1], acc[r]);
                acc[r] = fmaf(w.z, xq[c4 * 4 + 2], acc[r]);
                acc[r] = fmaf(w.w, xq[c4 * 4 + 3], acc[r]);
            }
        }
        float4 o;
        o.x = fmaxf(acc[0], 0.f); o.y = fmaxf(acc[1], 0.f);
        o.z = fmaxf(acc[2], 0.f); o.w = fmaxf(acc[3], 0.f);
        *(float4*)&rout[o0] = o;
    }

    float* hout = g_hb + (size_t)(b * 4096 + n) * 16;
#pragma unroll 1
    for (int o0 = 0; o0 < 16; o0 += 4) {
        float acc[4];
#pragma unroll
        for (int r = 0; r < 4; ++r) acc[r] = tbs[o0 + r];
#pragma unroll
        for (int c4 = 0; c4 < 16; ++c4) {
#pragma unroll
            for (int r = 0; r < 4; ++r) {
                float4 w = *(const float4*)&Wbs[(o0 + r) * 64 + c4 * 4];
                acc[r] = fmaf(w.x, xq[c4 * 4 + 0], acc[r]);
                acc[r] = fmaf(w.y, xq[c4 * 4 + 1], acc[r]);
                acc[r] = fmaf(w.z, xq[c4 * 4 + 2], acc[r]);
                acc[r] = fmaf(w.w, xq[c4 * 4 + 3], acc[r]);
            }
        }
        float4 o;
        o.x = fmaxf(acc[0], 0.f); o.y = fmaxf(acc[1], 0.f);
        o.z = fmaxf(acc[2], 0.f); o.w = fmaxf(acc[3], 0.f);
        *(float4*)&hout[o0] = o;
    }
}

// =====================================================================
// Kernel 2: fold W_dec with BN scale and transpose to [j][o]
// =====================================================================
__global__ void k_foldw(const float* __restrict__ Wd, const float* __restrict__ gd,
                        const float* __restrict__ vd)
{
    int li = blockIdx.x * blockDim.x + threadIdx.x;
    if (li < 96 * 128) {
        int j = li >> 7, o = li & 127;
        float s = gd[o] * rsqrtf(vd[o] + EPS);
        g_wdt[li] = Wd[o * 96 + j] * s;
    }
}

// =====================================================================
// Kernel 3a: KNN stage 1.
// grid (32 query-tiles, 4 candidate-columns, B).  256 thr = 128 queries
// x 2 splits of 16 candidates within each 32-candidate tile.
// Query channels live in smem (transposed, stride 68 -> conflict-free
// LDS.128), loaded into regs in 16-channel chunks => ~95 regs, 2 blk/SM.
// f32x2 packed FMAs; per-thread top-20 over 512 candidates; each block
// emits 2 stable-sorted partial lists per query.
// =====================================================================
struct __align__(16) KnnSm {
    float qT[128][68];    // transposed query tile (pad to 68 for LDS.128 bank-freedom)
    float ms[64][32];     // candidate tile, channel-major
    float sqm[32];
};

__global__ void __launch_bounds__(256, 2) k_knn1(const float* __restrict__ x)
{
    __shared__ KnnSm sm;
    int t = threadIdx.x;
    int q = t & 127, s = t >> 7;
    int b = blockIdx.z;
    int qg0 = blockIdx.x * 128;
    int m_base = blockIdx.y * 1024;
    const float* xb = x + (size_t)b * 64 * 4096;

    for (int li = t; li < 64 * 128; li += 256) {
        int c = li >> 7, n = li & 127;
        sm.qT[n][c] = xb[c * 4096 + qg0 + n];
    }

    float topd[20]; int topi[20];
#pragma unroll
    for (int j = 0; j < 20; ++j) { topd[j] = FLT_MAX; topi[j] = 0x7fffffff; }

    int cb = s * 16;
#pragma unroll 1
    for (int tile = 0; tile < 32; ++tile) {
        int m0 = m_base + tile * 32;
        __syncthreads();
        {
            int c = t >> 2;
            int col = (t & 3) * 8;
            *(float4*)&sm.ms[c][col]     = *(const float4*)&xb[c * 4096 + m0 + col];
            *(float4*)&sm.ms[c][col + 4] = *(const float4*)&xb[c * 4096 + m0 + col + 4];
        }
        if (t < 8)
            *(float4*)&sm.sqm[t * 4] = *(const float4*)&g_sq[b * 4096 + m0 + t * 4];
        __syncthreads();

        unsigned long long acc[8];
#pragma unroll
        for (int i = 0; i < 8; ++i) acc[i] = 0ull;

#pragma unroll
        for (int ch = 0; ch < 4; ++ch) {
            float qv[16];
#pragma unroll
            for (int c4 = 0; c4 < 4; ++c4)
                *(float4*)&qv[c4 * 4] = *(const float4*)&sm.qT[q][ch * 16 + c4 * 4];
#pragma unroll
            for (int cc = 0; cc < 16; ++cc) {
                unsigned long long qq = pack2(qv[cc]);
                const ulonglong2* mr = (const ulonglong2*)&sm.ms[ch * 16 + cc][cb];
                ulonglong2 v0 = mr[0], v1 = mr[1], v2 = mr[2], v3 = mr[3];
                acc[0] = fma2(qq, v0.x, acc[0]); acc[1] = fma2(qq, v0.y, acc[1]);
                acc[2] = fma2(qq, v1.x, acc[2]); acc[3] = fma2(qq, v1.y, acc[3]);
                acc[4] = fma2(qq, v2.x, acc[4]); acc[5] = fma2(qq, v2.y, acc[5]);
                acc[6] = fma2(qq, v3.x, acc[6]); acc[7] = fma2(qq, v3.y, acc[7]);
            }
        }

        float dd[16];
#pragma unroll
        for (int i = 0; i < 8; ++i) unpack2(acc[i], dd[i * 2], dd[i * 2 + 1]);

#pragma unroll
        for (int j = 0; j < 16; ++j) {
            float v = fmaf(-2.f, dd[j], sm.sqm[cb + j]);   // rank key; sq[query] dropped
            if (v < topd[19]) {
                float dv = v; int mi = m0 + cb + j;
#pragma unroll
                for (int jj = 0; jj < 20; ++jj) {
                    if (dv < topd[jj]) {
                        float td = topd[jj]; topd[jj] = dv; dv = td;
                        int ti = topi[jj]; topi[jj] = mi; mi = ti;
                    }
                }
            }
        }
    }

    int list = blockIdx.y * 2 + s;
    size_t base = (((size_t)b * 8 + list) * 4096 + qg0 + q) * 20;
#pragma unroll
    for (int j = 0; j < 20; ++j) { g_kd[base + j] = topd[j]; g_ki[base + j] = topi[j]; }
}

// =====================================================================
// Kernel 3b: KNN stage 2 — stable 8-way merge of partial lists.
// One thread per query.
// =====================================================================
__global__ void __launch_bounds__(256) k_knn2()
{
    int g = blockIdx.x * 256 + threadIdx.x;       // [0, 16384)
    int b = g >> 12, q = g & 4095;

    const float* dp[8]; const int* ip[8];
    float hd[8]; int hi[8]; int pos[8];
#pragma unroll
    for (int l = 0; l < 8; ++l) {
        size_t base = (((size_t)b * 8 + l) * 4096 + q) * 20;
        dp[l] = g_kd + base; ip[l] = g_ki + base;
        hd[l] = dp[l][0]; hi[l] = ip[l][0]; pos[l] = 0;
    }
    int* op = g_idx + (size_t)g * 20;
#pragma unroll 1
    for (int k = 0; k < 20; ++k) {
        float bd = hd[0]; int bi = hi[0]; int bl = 0;
#pragma unroll
        for (int l = 1; l < 8; ++l) {
            if (hd[l] < bd || (hd[l] == bd && hi[l] < bi)) { bd = hd[l]; bi = hi[l]; bl = l; }
        }
        op[k] = bi;
        int p = ++pos[bl];
        if (p < 20) { hd[bl] = dp[bl][p]; hi[bl] = ip[bl][p]; }
        else { hd[bl] = FLT_MAX; hi[bl] = 0x7fffffff; }
    }
}

// =====================================================================
// Kernel 4: epilogue.  one warp per point (8 points / 256-thr block).
// gather -> gcn1 (K=20) + gcn2 (even k) + global max -> decoder (W_dec
// staged through smem in 16-row chunks) + residual.
// =====================================================================
__global__ void __launch_bounds__(256) k_epilogue(
    const float* __restrict__ Wg1, const float* __restrict__ g1g, const float* __restrict__ g1b,
    const float* __restrict__ g1m, const float* __restrict__ g1v,
    const float* __restrict__ Wg2, const float* __restrict__ g2g, const float* __restrict__ g2b,
    const float* __restrict__ g2m, const float* __restrict__ g2v,
    const float* __restrict__ gdg, const float* __restrict__ gdb,
    const float* __restrict__ gdm, const float* __restrict__ gdv,
    float* __restrict__ out)
{
    __shared__ __align__(16) float W1s[32 * 32];   // [in][out], BN-folded
    __shared__ __align__(16) float W2s[32 * 32];
    __shared__ float t1s[32], t2s[32], s1s[32], s2s[32];
    __shared__ __align__(16) float tds[128];
    __shared__ __align__(16) float fns[8][20][16];
    __shared__ __align__(16) float ctrs[8][16];
    __shared__ float afs[8][96];
    __shared__ __align__(16) float wsm[16][128];   // W_dec chunk stage

    int t = threadIdx.x;
    if (t < 32)      { float s = g1g[t] * rsqrtf(g1v[t] + EPS); s1s[t] = s; t1s[t] = g1b[t] - g1m[t] * s; }
    else if (t < 64) { int i = t - 32; float s = g2g[i] * rsqrtf(g2v[i] + EPS); s2s[i] = s; t2s[i] = g2b[i] - g2m[i] * s; }
    if (t < 128)     { float s = gdg[t] * rsqrtf(gdv[t] + EPS); tds[t] = gdb[t] - gdm[t] * s; }
    __syncthreads();
    for (int li = t; li < 1024; li += 256) {
        int i = li >> 5, o = li & 31;
        W1s[li] = Wg1[o * 32 + i] * s1s[o];
        W2s[li] = Wg2[o * 32 + i] * s2s[o];
    }
    __syncthreads();

    int wid = t >> 5, lane = t & 31;
    int g = blockIdx.x * 8 + wid;
    int b = g >> 12, n = g & 4095;

    float* fw = &fns[wid][0][0];
    float* cw = &ctrs[wid][0];
    float* aw = &afs[wid][0];

    if (lane < 20) {
        int nid = g_idx[(size_t)g * 20 + lane];
        const float4* src = (const float4*)(g_hb + (size_t)(b * 4096 + nid) * 16);
        float4* dst = (float4*)(fw + lane * 16);
        dst[0] = src[0]; dst[1] = src[1]; dst[2] = src[2]; dst[3] = src[3];
    } else if (lane < 24) {
        int j = lane - 20;
        ((float4*)cw)[j] = ((const float4*)(g_hb + (size_t)g * 16))[j];
    }
    __syncwarp();

    float w1[32], w2[32];
#pragma unroll
    for (int i = 0; i < 32; ++i) { w1[i] = W1s[i * 32 + lane]; w2[i] = W2s[i * 32 + lane]; }

    // center contribution (channels 16..31 of the graph feature) hoisted
    float base1 = t1s[lane], base2 = t2s[lane];
#pragma unroll
    for (int j = 0; j < 16; ++j) {
        float cv = cw[j];
        base1 = fmaf(w1[16 + j], cv, base1);
        base2 = fmaf(w2[16 + j], cv, base2);
    }

    float o1 = -FLT_MAX, o2v = -FLT_MAX;
#pragma unroll
    for (int k = 0; k < 20; ++k) {
        const float4* fr = (const float4*)(fw + k * 16);
        float fv[16];
#pragma unroll
        for (int j4 = 0; j4 < 4; ++j4) {
            float4 fq = fr[j4];
            fv[j4 * 4 + 0] = fq.x; fv[j4 * 4 + 1] = fq.y;
            fv[j4 * 4 + 2] = fq.z; fv[j4 * 4 + 3] = fq.w;
        }
        float a = base1;
#pragma unroll
        for (int j = 0; j < 16; ++j) a = fmaf(w1[j], fv[j], a);
        a = a > 0.f ? a : 0.2f * a;        // leaky relu
        o1 = fmaxf(o1, a);
        if ((k & 1) == 0) {                // dilated branch: k = 0,2,...,18
            float a2 = base2;
#pragma unroll
            for (int j = 0; j < 16; ++j) a2 = fmaf(w2[j], fv[j], a2);
            a2 = a2 > 0.f ? a2 : 0.2f * a2;
            o2v = fmaxf(o2v, a2);
        }
    }

    // global max over f1: ch 0..15 = max over neighbors, ch 16..31 = center
    float gm;
    if (lane < 16) {
        gm = fw[lane];
#pragma unroll
        for (int k = 1; k < 20; ++k) gm = fmaxf(gm, fw[k * 16 + lane]);
    } else {
        gm = cw[lane - 16];
    }
    aw[lane] = o1; aw[32 + lane] = o2v; aw[64 + lane] = gm;
    __syncwarp();

    // decoder: lane handles outputs o = 4*lane .. 4*lane+3; W_dec staged
    // through smem in 16-row chunks shared by all 8 warps
    float4 acc = *(const float4*)&tds[lane * 4];
#pragma unroll 1
    for (int j0 = 0; j0 < 96; j0 += 16) {
        __syncthreads();
        for (int li = t; li < 16 * 128; li += 256)
            wsm[li >> 7][li & 127] = g_wdt[(j0 << 7) + li];
        __syncthreads();
#pragma unroll
        for (int jj = 0; jj < 16; ++jj) {
            float a = aw[j0 + jj];
            float4 w = *(const float4*)&wsm[jj][lane * 4];
            acc.x = fmaf(w.x, a, acc.x); acc.y = fmaf(w.y, a, acc.y);
            acc.z = fmaf(w.z, a, acc.z); acc.w = fmaf(w.w, a, acc.w);
        }
    }
    const float4 rv = *(const float4*)(g_rt + (size_t)g * 128 + lane * 4);
    float r0 = fmaxf(acc.x, 0.f) + rv.x;
    float r1 = fmaxf(acc.y, 0.f) + rv.y;
    float r2 = fmaxf(acc.z, 0.f) + rv.z;
    float r3 = fmaxf(acc.w, 0.f) + rv.w;

    size_t ob = ((size_t)b * 128 + lane * 4) * 4096 + n;   // out[b][o][n][0]
    out[ob]            = r0;
    out[ob + 4096]     = r1;
    out[ob + 2 * 4096] = r2;
    out[ob + 3 * 4096] = r3;
}

// =====================================================================
extern "C" void kernel_launch(void* const* d_in, const int* in_sizes, int n_in,
                              void* d_out, int out_size)
{
    (void)in_sizes; (void)n_in; (void)out_size;
    const float* x    = (const float*)d_in[0];
    const float* Wr   = (const float*)d_in[1];
    const float* gr   = (const float*)d_in[2];
    const float* br   = (const float*)d_in[3];
    const float* mr   = (const float*)d_in[4];
    const float* vr   = (const float*)d_in[5];
    const float* Wb   = (const float*)d_in[6];
    const float* gb   = (const float*)d_in[7];
    const float* bbi  = (const float*)d_in[8];
    const float* mb   = (const float*)d_in[9];
    const float* vb   = (const float*)d_in[10];
    const float* Wg1  = (const float*)d_in[11];
    const float* g1g  = (const float*)d_in[12];
    const float* g1b  = (const float*)d_in[13];
    const float* g1m  = (const float*)d_in[14];
    const float* g1v  = (const float*)d_in[15];
    const float* Wg2  = (const float*)d_in[16];
    const float* g2g  = (const float*)d_in[17];
    const float* g2b  = (const float*)d_in[18];
    const float* g2m  = (const float*)d_in[19];
    const float* g2v  = (const float*)d_in[20];
    const float* Wd   = (const float*)d_in[21];
    const float* gdg  = (const float*)d_in[22];
    const float* gdb  = (const float*)d_in[23];
    const float* gdm  = (const float*)d_in[24];
    const float* gdv  = (const float*)d_in[25];
    float* out = (float*)d_out;

    k_prologue<<<dim3(32, 4), 128>>>(x, Wr, gr, br, mr, vr, Wb, gb, bbi, mb, vb);
    k_foldw<<<48, 256>>>(Wd, gdg, gdv);
    k_knn1<<<dim3(32, 4, 4), 256>>>(x);
    k_knn2<<<64, 256>>>();
    k_epilogue<<<2048, 256>>>(Wg1, g1g, g1b, g1m, g1v,
                              Wg2, g2g, g2b, g2m, g2v,
                              gdg, gdb, gdm, gdv, out);
}